// round 3
// baseline (speedup 1.0000x reference)
#include <cuda_runtime.h>
#include <cuda_fp16.h>

#define D          128
#define TILE_R     96
#define NTHREADS   384
#define S4         96          // float4 row stride for XsP4/CsQ4 (rows dimension)

typedef unsigned long long u64;

// Packed dual-fp32 FMA: acc.lo += a.lo*b.lo ; acc.hi += a.hi*b.hi  (sm_100+ FFMA2)
__device__ __forceinline__ void fma2(u64 &acc, u64 a, u64 b) {
    asm("fma.rn.f32x2 %0, %1, %2, %0;" : "+l"(acc) : "l"(a), "l"(b));
}
__device__ __forceinline__ float f2lo(u64 v) { return __uint_as_float((unsigned)(v & 0xffffffffull)); }
__device__ __forceinline__ float f2hi(u64 v) { return __uint_as_float((unsigned)(v >> 32)); }

// Shared layout (float4 units):
//   PiP4 [32][128] : PiP4[kp2][c] = (Pi[c][4kp2], Pi[c][4kp2+1], Pi[c][4kp2+2], Pi[c][4kp2+3])
//   PiQ4 [32][128] : PiQ4[jp2][k] = (Pi[4jp2][k], Pi[4jp2+1][k], Pi[4jp2+2][k], Pi[4jp2+3][k])
//   XsP4 [32][S4]  : XsP4[kp2][r] = normalized x[r][4kp2 .. 4kp2+3]
//   CsQ4 [32][S4]  : CsQ4[jp2][r] = centroid values for cols 4jp2 .. 4jp2+3 of row r
#define SMEM_FLOATS (32*128*4*2 + 32*S4*4*2 + TILE_R + 16 + 15)
#define SMEM_BYTES  (SMEM_FLOATS * 4)

__global__ void __launch_bounds__(NTHREADS, 1)
tq_kernel(const float* __restrict__ x, const float* __restrict__ Pi,
          const float* __restrict__ cent, const float* __restrict__ bnd,
          float* __restrict__ out, int n_rows, int ntiles)
{
    extern __shared__ float4 smem4[];
    float4* PiP4 = smem4;
    float4* PiQ4 = PiP4 + 32 * 128;
    float4* XsP4 = PiQ4 + 32 * 128;
    float4* CsQ4 = XsP4 + 32 * S4;
    float*  CsQf = (float*)CsQ4;
    float*  norm16_s = (float*)(CsQ4 + 32 * S4);   // [TILE_R]
    float*  cent_s   = norm16_s + TILE_R;          // [16]
    float*  bnd_s    = cent_s + 16;                // [15]

    const int tid = threadIdx.x;

    // ---- one-time per block: pack Pi both ways, stage centroids/boundaries ----
    for (int i = tid; i < 32 * 128; i += NTHREADS) {
        int a = i >> 7;        // kp2 (PiP4) / jp2 (PiQ4)
        int b = i & 127;       // c   (PiP4) / k   (PiQ4)
        PiP4[i] = *(const float4*)(Pi + b * 128 + 4 * a);
        PiQ4[i] = make_float4(Pi[(4 * a) * 128 + b], Pi[(4 * a + 1) * 128 + b],
                              Pi[(4 * a + 2) * 128 + b], Pi[(4 * a + 3) * 128 + b]);
    }
    if (tid < 16) cent_s[tid] = cent[tid];
    if (tid < 15) bnd_s[tid] = bnd[tid + 1];
    __syncthreads();

    const int ty = tid >> 4;           // 0..23 : row group
    const int tx = tid & 15;           // 0..15 : column lane
    const int r0 = ty * 4;             // 4 rows per thread
    // column ownership: c = tx + 16*jj, jj = 0..7

    for (int tile = blockIdx.x; tile < ntiles; tile += gridDim.x) {

        // ================= phase 1: load, norm, normalize, pack =================
        {
            const int rl = tid >> 2;            // local row 0..95
            const int l  = tid & 3;             // 4 lanes per row
            const int grow = tile * TILE_R + rl;
            float4 v[8];
            float ss = 0.0f;
            if (grow < n_rows) {
                const float* xr = x + (size_t)grow * D;
                #pragma unroll
                for (int c = 0; c < 8; c++) {
                    v[c] = *(const float4*)(xr + 16 * c + 4 * l);
                    ss += v[c].x * v[c].x + v[c].y * v[c].y + v[c].z * v[c].z + v[c].w * v[c].w;
                }
            } else {
                #pragma unroll
                for (int c = 0; c < 8; c++) v[c] = make_float4(0.f, 0.f, 0.f, 0.f);
            }
            ss += __shfl_xor_sync(0xffffffffu, ss, 1);
            ss += __shfl_xor_sync(0xffffffffu, ss, 2);
            float nrm = __fsqrt_rn(ss);
            float den = nrm + 1e-8f;
            if (l == 0) norm16_s[rl] = __half2float(__float2half_rn(nrm));
            #pragma unroll
            for (int c = 0; c < 8; c++) {
                float4 a4;
                a4.x = __fdiv_rn(v[c].x, den);
                a4.y = __fdiv_rn(v[c].y, den);
                a4.z = __fdiv_rn(v[c].z, den);
                a4.w = __fdiv_rn(v[c].w, den);
                XsP4[(4 * c + l) * S4 + rl] = a4;   // k-chunk (16c+4l)/4
            }
        }
        __syncthreads();

        // ================= GEMM1: rot[r][c] = sum_k xn[r][k] * Pi[c][k] =================
        u64 acc[4][8][2];
        #pragma unroll
        for (int i = 0; i < 4; i++)
            #pragma unroll
            for (int j = 0; j < 8; j++) { acc[i][j][0] = 0ull; acc[i][j][1] = 0ull; }

        #pragma unroll 2
        for (int kp2 = 0; kp2 < 32; kp2++) {
            float4 xv[4], pv[8];
            #pragma unroll
            for (int i = 0; i < 4; i++)
                xv[i] = XsP4[kp2 * S4 + r0 + i];
            #pragma unroll
            for (int jj = 0; jj < 8; jj++)
                pv[jj] = PiP4[kp2 * 128 + tx + 16 * jj];
            #pragma unroll
            for (int i = 0; i < 4; i++) {
                u64 xlo = *(u64*)&xv[i].x, xhi = *(u64*)&xv[i].z;
                #pragma unroll
                for (int jj = 0; jj < 8; jj++) {
                    fma2(acc[i][jj][0], xlo, *(u64*)&pv[jj].x);
                    fma2(acc[i][jj][1], xhi, *(u64*)&pv[jj].z);
                }
            }
        }

        // ================= quantize (searchsorted left) + centroid gather =================
        {
            float breg[15];
            #pragma unroll
            for (int t = 0; t < 15; t++) breg[t] = bnd_s[t];
            #pragma unroll
            for (int i = 0; i < 4; i++) {
                #pragma unroll
                for (int jj = 0; jj < 8; jj++) {
                    u64 s0 = acc[i][jj][0], s1 = acc[i][jj][1];
                    float v0 = (f2lo(s0) + f2hi(s0)) + (f2lo(s1) + f2hi(s1));
                    int i0 = 0;
                    #pragma unroll
                    for (int t = 0; t < 15; t++) i0 += (v0 > breg[t]);
                    int c = tx + 16 * jj;
                    CsQf[((c >> 2) * S4 + r0 + i) * 4 + (c & 3)] = cent_s[i0];
                }
            }
        }
        __syncthreads();

        // ================= GEMM2: rec[r][k] = sum_j cval[r][j] * Pi[j][k] =================
        u64 oac[4][8][2];
        #pragma unroll
        for (int i = 0; i < 4; i++)
            #pragma unroll
            for (int j = 0; j < 8; j++) { oac[i][j][0] = 0ull; oac[i][j][1] = 0ull; }

        #pragma unroll 2
        for (int jp2 = 0; jp2 < 32; jp2++) {
            float4 cv[4], pv[8];
            #pragma unroll
            for (int i = 0; i < 4; i++)
                cv[i] = CsQ4[jp2 * S4 + r0 + i];
            #pragma unroll
            for (int jj = 0; jj < 8; jj++)
                pv[jj] = PiQ4[jp2 * 128 + tx + 16 * jj];
            #pragma unroll
            for (int i = 0; i < 4; i++) {
                u64 clo = *(u64*)&cv[i].x, chi = *(u64*)&cv[i].z;
                #pragma unroll
                for (int jj = 0; jj < 8; jj++) {
                    fma2(oac[i][jj][0], clo, *(u64*)&pv[jj].x);
                    fma2(oac[i][jj][1], chi, *(u64*)&pv[jj].z);
                }
            }
        }

        // ================= scale by fp16-rounded norm, store =================
        #pragma unroll
        for (int i = 0; i < 4; i++) {
            int grow = tile * TILE_R + r0 + i;
            if (grow < n_rows) {
                float s = norm16_s[r0 + i];
                float* op = out + (size_t)grow * D;
                #pragma unroll
                for (int jj = 0; jj < 8; jj++) {
                    u64 s0 = oac[i][jj][0], s1 = oac[i][jj][1];
                    op[tx + 16 * jj] = ((f2lo(s0) + f2hi(s0)) + (f2lo(s1) + f2hi(s1))) * s;
                }
            }
        }
        __syncthreads();   // protect XsP4/CsQ4/norm16_s before next tile's phase 1
    }
}

extern "C" void kernel_launch(void* const* d_in, const int* in_sizes, int n_in,
                              void* d_out, int out_size)
{
    const float* x    = (const float*)d_in[0];   // [B,H,S,128] fp32
    const float* Pi   = (const float*)d_in[1];   // [128,128]
    const float* cent = (const float*)d_in[2];   // [16]
    const float* bnd  = (const float*)d_in[3];   // [17]
    float* out = (float*)d_out;

    int n_rows = in_sizes[0] / D;
    int ntiles = (n_rows + TILE_R - 1) / TILE_R;

    cudaFuncSetAttribute(tq_kernel, cudaFuncAttributeMaxDynamicSharedMemorySize, SMEM_BYTES);

    int dev = 0, sms = 148;
    cudaGetDevice(&dev);
    cudaDeviceGetAttribute(&sms, cudaDevAttrMultiProcessorCount, dev);
    int grid = (ntiles < sms) ? ntiles : sms;   // persistent: one block per SM

    tq_kernel<<<grid, NTHREADS, SMEM_BYTES>>>(x, Pi, cent, bnd, out, n_rows, ntiles);
}

// round 4
// speedup vs baseline: 1.4712x; 1.4712x over previous
#include <cuda_runtime.h>
#include <cuda_fp16.h>

#define D          128
#define TILE_R     96
#define NTHREADS   384
#define S4         96          // float4 row stride for XsP4/CsQ4 (rows dimension)

typedef unsigned long long u64;

// Packed dual-fp32 FMA: acc.lo += a.lo*b.lo ; acc.hi += a.hi*b.hi  (sm_100+ FFMA2)
__device__ __forceinline__ void fma2(u64 &acc, u64 a, u64 b) {
    asm("fma.rn.f32x2 %0, %1, %2, %0;" : "+l"(acc) : "l"(a), "l"(b));
}
__device__ __forceinline__ float f2lo(u64 v) { return __uint_as_float((unsigned)(v & 0xffffffffull)); }
__device__ __forceinline__ float f2hi(u64 v) { return __uint_as_float((unsigned)(v >> 32)); }

// Shared layout (float4 units):
//   PiP4 [32][128] : PiP4[kp2][c] = (Pi[c][4kp2], Pi[c][4kp2+1], Pi[c][4kp2+2], Pi[c][4kp2+3])
//   PiQ4 [32][128] : PiQ4[jp2][k] = (Pi[4jp2][k], Pi[4jp2+1][k], Pi[4jp2+2][k], Pi[4jp2+3][k])
//   XsP4 [32][S4]  : XsP4[kp2][r] = normalized x[r][4kp2 .. 4kp2+3]
//   CsQ4 [32][S4]  : CsQ4[jp2][r] = centroid values for cols 4jp2 .. 4jp2+3 of row r
#define SMEM_FLOATS (32*128*4*2 + 32*S4*4*2 + TILE_R + 16 + 15)
#define SMEM_BYTES  (SMEM_FLOATS * 4)

__global__ void __launch_bounds__(NTHREADS, 1)
tq_kernel(const float* __restrict__ x, const float* __restrict__ Pi,
          const float* __restrict__ cent, const float* __restrict__ bnd,
          float* __restrict__ out, int n_rows, int ntiles)
{
    extern __shared__ float4 smem4[];
    float4* PiP4 = smem4;
    float4* PiQ4 = PiP4 + 32 * 128;
    float4* XsP4 = PiQ4 + 32 * 128;
    float4* CsQ4 = XsP4 + 32 * S4;
    float*  CsQf = (float*)CsQ4;
    float*  norm16_s = (float*)(CsQ4 + 32 * S4);   // [TILE_R]
    float*  cent_s   = norm16_s + TILE_R;          // [16]
    float*  bnd_s    = cent_s + 16;                // [15]

    const int tid = threadIdx.x;

    // ---- one-time per block: pack Pi both ways, stage centroids/boundaries ----
    for (int i = tid; i < 32 * 128; i += NTHREADS) {
        int a = i >> 7;        // kp2 (PiP4) / jp2 (PiQ4)
        int b = i & 127;       // c   (PiP4) / k   (PiQ4)
        PiP4[i] = *(const float4*)(Pi + b * 128 + 4 * a);
        PiQ4[i] = make_float4(Pi[(4 * a) * 128 + b], Pi[(4 * a + 1) * 128 + b],
                              Pi[(4 * a + 2) * 128 + b], Pi[(4 * a + 3) * 128 + b]);
    }
    if (tid < 16) cent_s[tid] = cent[tid];
    if (tid < 15) bnd_s[tid] = bnd[tid + 1];
    __syncthreads();

    const int ty = tid >> 4;           // 0..23 : row group
    const int tx = tid & 15;           // 0..15 : column lane
    const int r0 = ty * 4;             // 4 rows per thread
    // column ownership: c = tx + 16*jj, jj = 0..7

    for (int tile = blockIdx.x; tile < ntiles; tile += gridDim.x) {

        // ================= phase 1: load, norm, normalize, pack =================
        {
            const int rl = tid >> 2;            // local row 0..95
            const int l  = tid & 3;             // 4 lanes per row
            const int grow = tile * TILE_R + rl;
            float4 v[8];
            float ss = 0.0f;
            if (grow < n_rows) {
                const float* xr = x + (size_t)grow * D;
                #pragma unroll
                for (int c = 0; c < 8; c++) {
                    v[c] = *(const float4*)(xr + 16 * c + 4 * l);
                    ss += v[c].x * v[c].x + v[c].y * v[c].y + v[c].z * v[c].z + v[c].w * v[c].w;
                }
            } else {
                #pragma unroll
                for (int c = 0; c < 8; c++) v[c] = make_float4(0.f, 0.f, 0.f, 0.f);
            }
            ss += __shfl_xor_sync(0xffffffffu, ss, 1);
            ss += __shfl_xor_sync(0xffffffffu, ss, 2);
            float nrm = __fsqrt_rn(ss);
            float den = nrm + 1e-8f;
            if (l == 0) norm16_s[rl] = __half2float(__float2half_rn(nrm));
            #pragma unroll
            for (int c = 0; c < 8; c++) {
                float4 a4;
                a4.x = __fdiv_rn(v[c].x, den);
                a4.y = __fdiv_rn(v[c].y, den);
                a4.z = __fdiv_rn(v[c].z, den);
                a4.w = __fdiv_rn(v[c].w, den);
                XsP4[(4 * c + l) * S4 + rl] = a4;   // k-chunk (16c+4l)/4
            }
        }
        __syncthreads();

        // ================= GEMM1: rot[r][c] = sum_k xn[r][k] * Pi[c][k] =================
        // Single u64 accumulator per (i,jj): lo holds even-k partial sums, hi odd-k.
        u64 acc[4][8];
        #pragma unroll
        for (int i = 0; i < 4; i++)
            #pragma unroll
            for (int j = 0; j < 8; j++) acc[i][j] = 0ull;

        #pragma unroll 2
        for (int kp2 = 0; kp2 < 32; kp2++) {
            float4 xv[4], pv[8];
            #pragma unroll
            for (int i = 0; i < 4; i++)
                xv[i] = XsP4[kp2 * S4 + r0 + i];
            #pragma unroll
            for (int jj = 0; jj < 8; jj++)
                pv[jj] = PiP4[kp2 * 128 + tx + 16 * jj];
            #pragma unroll
            for (int i = 0; i < 4; i++) {
                u64 xlo = *(u64*)&xv[i].x, xhi = *(u64*)&xv[i].z;
                #pragma unroll
                for (int jj = 0; jj < 8; jj++) {
                    fma2(acc[i][jj], xlo, *(u64*)&pv[jj].x);
                    fma2(acc[i][jj], xhi, *(u64*)&pv[jj].z);
                }
            }
        }

        // ================= quantize (searchsorted left) + centroid gather =================
        {
            float breg[15];
            #pragma unroll
            for (int t = 0; t < 15; t++) breg[t] = bnd_s[t];
            #pragma unroll
            for (int i = 0; i < 4; i++) {
                #pragma unroll
                for (int jj = 0; jj < 8; jj++) {
                    float v0 = f2lo(acc[i][jj]) + f2hi(acc[i][jj]);
                    int i0 = 0;
                    #pragma unroll
                    for (int t = 0; t < 15; t++) i0 += (v0 > breg[t]);
                    int c = tx + 16 * jj;
                    CsQf[((c >> 2) * S4 + r0 + i) * 4 + (c & 3)] = cent_s[i0];
                }
            }
        }
        __syncthreads();

        // ================= GEMM2: rec[r][k] = sum_j cval[r][j] * Pi[j][k] =================
        u64 oac[4][8];
        #pragma unroll
        for (int i = 0; i < 4; i++)
            #pragma unroll
            for (int j = 0; j < 8; j++) oac[i][j] = 0ull;

        #pragma unroll 2
        for (int jp2 = 0; jp2 < 32; jp2++) {
            float4 cv[4], pv[8];
            #pragma unroll
            for (int i = 0; i < 4; i++)
                cv[i] = CsQ4[jp2 * S4 + r0 + i];
            #pragma unroll
            for (int jj = 0; jj < 8; jj++)
                pv[jj] = PiQ4[jp2 * 128 + tx + 16 * jj];
            #pragma unroll
            for (int i = 0; i < 4; i++) {
                u64 clo = *(u64*)&cv[i].x, chi = *(u64*)&cv[i].z;
                #pragma unroll
                for (int jj = 0; jj < 8; jj++) {
                    fma2(oac[i][jj], clo, *(u64*)&pv[jj].x);
                    fma2(oac[i][jj], chi, *(u64*)&pv[jj].z);
                }
            }
        }

        // ================= scale by fp16-rounded norm, store =================
        #pragma unroll
        for (int i = 0; i < 4; i++) {
            int grow = tile * TILE_R + r0 + i;
            if (grow < n_rows) {
                float s = norm16_s[r0 + i];
                float* op = out + (size_t)grow * D;
                #pragma unroll
                for (int jj = 0; jj < 8; jj++)
                    op[tx + 16 * jj] = (f2lo(oac[i][jj]) + f2hi(oac[i][jj])) * s;
            }
        }
        __syncthreads();   // protect XsP4/CsQ4/norm16_s before next tile's phase 1
    }
}

extern "C" void kernel_launch(void* const* d_in, const int* in_sizes, int n_in,
                              void* d_out, int out_size)
{
    const float* x    = (const float*)d_in[0];   // [B,H,S,128] fp32
    const float* Pi   = (const float*)d_in[1];   // [128,128]
    const float* cent = (const float*)d_in[2];   // [16]
    const float* bnd  = (const float*)d_in[3];   // [17]
    float* out = (float*)d_out;

    int n_rows = in_sizes[0] / D;
    int ntiles = (n_rows + TILE_R - 1) / TILE_R;

    cudaFuncSetAttribute(tq_kernel, cudaFuncAttributeMaxDynamicSharedMemorySize, SMEM_BYTES);

    int dev = 0, sms = 148;
    cudaGetDevice(&dev);
    cudaDeviceGetAttribute(&sms, cudaDevAttrMultiProcessorCount, dev);
    int grid = (ntiles < sms) ? ntiles : sms;   // persistent: one block per SM

    tq_kernel<<<grid, NTHREADS, SMEM_BYTES>>>(x, Pi, cent, bnd, out, n_rows, ntiles);
}